// round 13
// baseline (speedup 1.0000x reference)
#include <cuda_runtime.h>

// ---------------------------------------------------------------------------
// Problem constants
// ---------------------------------------------------------------------------
#define TT   512
#define BB   1024
#define IN1  80
#define NH1  100
#define NG1  400
#define NH2  50
#define NG2  200

typedef unsigned long long ull;

// ---------------------------------------------------------------------------
// Device scratch
// ---------------------------------------------------------------------------
__device__ __align__(16) float g_pre1[(size_t)BB * TT * NG1];   // [b][t][400]
__device__ __align__(16) float g_h1  [(size_t)BB * TT * NH1];   // [b][t][100]
__device__ __align__(16) float g_pre2[(size_t)BB * TT * NG2];   // [b][t][200]

// MMA frag-ordered weights (bf16 hi/lo splits), layout [panel][kt][nt][lane]
__device__ __align__(16) ull g_w1fh[2 * 5 * 25 * 32];   // gemm1 hi
__device__ __align__(16) ull g_w1fl[2 * 5 * 25 * 32];   // gemm1 lo
__device__ __align__(16) ull g_w2fh[7 * 25 * 32];       // gemm2 hi (K padded 112)
__device__ __align__(16) ull g_w2fl[7 * 25 * 32];       // gemm2 lo
// LSTM recurrent weights: plain [k][g]
__device__ __align__(16) float g_whh1T[NH1 * NG1];
__device__ __align__(16) float g_whh2T[NH2 * NG2];
// Fused biases, zero-padded
__device__ __align__(16) float g_b1[512];
__device__ __align__(16) float g_b2[512];

// ---------------------------------------------------------------------------
// helpers
// ---------------------------------------------------------------------------
__device__ __forceinline__ ull ffma2(ull d, ull a, ull b) {
    asm("fma.rn.f32x2 %0, %1, %2, %0;" : "+l"(d) : "l"(a), "l"(b));
    return d;
}
__device__ __forceinline__ ull dup2(float x) {
    ull r; unsigned u = __float_as_uint(x);
    asm("mov.b64 %0, {%1, %1};" : "=l"(r) : "r"(u));
    return r;
}
__device__ __forceinline__ ull pk(float x, float y) {
    ull r;
    asm("mov.b64 %0, {%1, %2};" : "=l"(r) : "f"(x), "f"(y));
    return r;
}
__device__ __forceinline__ void upk(ull v, float& a, float& b) {
    unsigned lo, hi;
    asm("mov.b64 {%0, %1}, %2;" : "=r"(lo), "=r"(hi) : "l"(v));
    a = __uint_as_float(lo); b = __uint_as_float(hi);
}
// pack two f32 into bf16x2: first arg -> UPPER half, second -> LOWER half
__device__ __forceinline__ unsigned pkbf(float hi_elem, float lo_elem) {
    unsigned r;
    asm("cvt.rn.bf16x2.f32 %0, %1, %2;" : "=r"(r) : "f"(hi_elem), "f"(lo_elem));
    return r;
}
__device__ __forceinline__ float bflo_f(unsigned p) { return __uint_as_float(p << 16); }
__device__ __forceinline__ float bfhi_f(unsigned p) { return __uint_as_float(p & 0xffff0000u); }

// m16n8k16 row.col bf16 MMA, fp32 accumulate
__device__ __forceinline__ void mma16816(float& c0, float& c1, float& c2, float& c3,
                                         const unsigned* a, unsigned b0, unsigned b1) {
    asm volatile(
        "mma.sync.aligned.m16n8k16.row.col.f32.bf16.bf16.f32 "
        "{%0,%1,%2,%3}, {%4,%5,%6,%7}, {%8,%9}, {%0,%1,%2,%3};"
        : "+f"(c0), "+f"(c1), "+f"(c2), "+f"(c3)
        : "r"(a[0]), "r"(a[1]), "r"(a[2]), "r"(a[3]), "r"(b0), "r"(b1));
}

// MUFU-based activations (tanh.approx: 1 MUFU, ~2^-11 abs err)
__device__ __forceinline__ float tanh_m(float x) {
    float r; asm("tanh.approx.f32 %0, %1;" : "=f"(r) : "f"(x));
    return r;
}
__device__ __forceinline__ float sigm_m(float x) {
    return fmaf(0.5f, tanh_m(0.5f * x), 0.5f);
}

// ---------------------------------------------------------------------------
// prep: build frag-ordered bf16 hi/lo weights, LSTM weights, biases
// ---------------------------------------------------------------------------
__global__ void prep_kernel(const float* __restrict__ Wih1, const float* __restrict__ Whh1,
                            const float* __restrict__ bih1, const float* __restrict__ bhh1,
                            const float* __restrict__ Wih2, const float* __restrict__ Whh2,
                            const float* __restrict__ bih2, const float* __restrict__ bhh2) {
    int tid = blockIdx.x * blockDim.x + threadIdx.x;
    int stride = gridDim.x * blockDim.x;

    for (int i = tid; i < 2 * 5 * 25 * 32; i += stride) {
        int l = i & 31, t = i >> 5;
        int nt = t % 25; t /= 25;
        int kt = t % 5;  int p = t / 5;
        int n  = (p * 25 + nt) * 8 + (l >> 2);
        int k0 = 16 * kt + 2 * (l & 3);
        float w0 = Wih1[n * IN1 + k0];
        float w1 = Wih1[n * IN1 + k0 + 1];
        float w2 = Wih1[n * IN1 + k0 + 8];
        float w3 = Wih1[n * IN1 + k0 + 9];
        unsigned h0 = pkbf(w1, w0), h1 = pkbf(w3, w2);
        unsigned l0 = pkbf(w1 - bfhi_f(h0), w0 - bflo_f(h0));
        unsigned l1 = pkbf(w3 - bfhi_f(h1), w2 - bflo_f(h1));
        g_w1fh[i] = (ull)h0 | ((ull)h1 << 32);
        g_w1fl[i] = (ull)l0 | ((ull)l1 << 32);
    }
    for (int i = tid; i < 7 * 25 * 32; i += stride) {
        int l = i & 31, t = i >> 5;
        int nt = t % 25;
        int kt = t / 25;
        int n  = nt * 8 + (l >> 2);
        int k0 = 16 * kt + 2 * (l & 3);
        float w0 = (k0     < NH1) ? Wih2[n * NH1 + k0]     : 0.0f;
        float w1 = (k0 + 1 < NH1) ? Wih2[n * NH1 + k0 + 1] : 0.0f;
        float w2 = (k0 + 8 < NH1) ? Wih2[n * NH1 + k0 + 8] : 0.0f;
        float w3 = (k0 + 9 < NH1) ? Wih2[n * NH1 + k0 + 9] : 0.0f;
        unsigned h0 = pkbf(w1, w0), h1 = pkbf(w3, w2);
        unsigned l0 = pkbf(w1 - bfhi_f(h0), w0 - bflo_f(h0));
        unsigned l1 = pkbf(w3 - bfhi_f(h1), w2 - bflo_f(h1));
        g_w2fh[i] = (ull)h0 | ((ull)h1 << 32);
        g_w2fl[i] = (ull)l0 | ((ull)l1 << 32);
    }
    for (int i = tid; i < NH1 * NG1; i += stride) { int k = i / NG1, g = i % NG1; g_whh1T[i] = Whh1[g * NH1 + k]; }
    for (int i = tid; i < NH2 * NG2; i += stride) { int k = i / NG2, g = i % NG2; g_whh2T[i] = Whh2[g * NH2 + k]; }
    for (int i = tid; i < 512; i += stride) {
        g_b1[i] = (i < NG1) ? bih1[i] + bhh1[i] : 0.0f;
        g_b2[i] = (i < NG2) ? bih2[i] + bhh2[i] : 0.0f;
    }
}

// ---------------------------------------------------------------------------
// Tensor-core GEMM v3: R7 shape (M=128, 8 warps, 2 CTAs/SM) + 2-way n-tile
// interleave: two independent accumulator chains per warp double tensor ILP.
// ---------------------------------------------------------------------------
template<int KT, int NTP, int KREAL, int G>
__global__ __launch_bounds__(256, 2)
void mma_gemm(const float* __restrict__ x, const ull* __restrict__ wfh,
              const ull* __restrict__ wfl, const float* __restrict__ bias,
              float* __restrict__ out) {
    constexpr int K = KT * 16;
    constexpr int NFRAG = KT * NTP * 32;
    constexpr int NPAIR = NTP / 2;           // interleaved pairs (12)
    extern __shared__ ull smw[];
    ull* shi = smw;
    ull* slo = smw + NFRAG;

    int tid  = threadIdx.x;
    int lane = tid & 31;
    int wi   = tid >> 5;
    int m0   = blockIdx.x * 128;
    int pb   = blockIdx.y;

    const ull* srch = wfh + (size_t)pb * NFRAG;
    const ull* srcl = wfl + (size_t)pb * NFRAG;
    for (int i = tid; i < NFRAG; i += 256) { shi[i] = srch[i]; slo[i] = srcl[i]; }
    __syncthreads();

    int r0 = m0 + wi * 16 + (lane >> 2);
    int r1 = r0 + 8;
    int cb = 2 * (lane & 3);

    unsigned ahi[KT][4], alo[KT][4];
#pragma unroll
    for (int kt = 0; kt < KT; kt++) {
#pragma unroll
        for (int q = 0; q < 4; q++) {
            int rr = (q & 1) ? r1 : r0;
            int cc = 16 * kt + cb + (q >> 1) * 8;
            float2 v = make_float2(0.0f, 0.0f);
            if (K == KREAL || cc + 2 <= KREAL)
                v = *(const float2*)(x + (size_t)rr * KREAL + cc);
            unsigned h = pkbf(v.y, v.x);
            ahi[kt][q] = h;
            alo[kt][q] = pkbf(v.y - bfhi_f(h), v.x - bflo_f(h));
        }
    }

    // interleaved pairs of n-tiles: 2 independent accumulator chains
    for (int np = 0; np < NPAIR; np++) {
        int ntA = 2 * np, ntB = 2 * np + 1;
        int ngA = (pb * NTP + ntA) * 8 + cb;
        int ngB = (pb * NTP + ntB) * 8 + cb;
        float2 bvA = *(const float2*)(bias + ngA);
        float2 bvB = *(const float2*)(bias + ngB);
        float a0 = bvA.x, a1 = bvA.y, a2 = bvA.x, a3 = bvA.y;
        float b0 = bvB.x, b1 = bvB.y, b2 = bvB.x, b3 = bvB.y;
        const ull* phA = shi + ntA * 32 + lane;
        const ull* plA = slo + ntA * 32 + lane;
        const ull* phB = shi + ntB * 32 + lane;
        const ull* plB = slo + ntB * 32 + lane;
#pragma unroll
        for (int kt = 0; kt < KT; kt++) {
            ull vhA = phA[kt * NTP * 32];
            ull vlA = plA[kt * NTP * 32];
            ull vhB = phB[kt * NTP * 32];
            ull vlB = plB[kt * NTP * 32];
            unsigned hA0 = (unsigned)vhA, hA1 = (unsigned)(vhA >> 32);
            unsigned lA0 = (unsigned)vlA, lA1 = (unsigned)(vlA >> 32);
            unsigned hB0 = (unsigned)vhB, hB1 = (unsigned)(vhB >> 32);
            unsigned lB0 = (unsigned)vlB, lB1 = (unsigned)(vlB >> 32);
            mma16816(a0, a1, a2, a3, ahi[kt], lA0, lA1);
            mma16816(b0, b1, b2, b3, ahi[kt], lB0, lB1);
            mma16816(a0, a1, a2, a3, alo[kt], hA0, hA1);
            mma16816(b0, b1, b2, b3, alo[kt], hB0, hB1);
            mma16816(a0, a1, a2, a3, ahi[kt], hA0, hA1);
            mma16816(b0, b1, b2, b3, ahi[kt], hB0, hB1);
        }
        *(float2*)(out + (size_t)r0 * G + ngA) = make_float2(a0, a1);
        *(float2*)(out + (size_t)r1 * G + ngA) = make_float2(a2, a3);
        *(float2*)(out + (size_t)r0 * G + ngB) = make_float2(b0, b1);
        *(float2*)(out + (size_t)r1 * G + ngB) = make_float2(b2, b3);
    }

    // tail n-tile (NTP odd)
    if (NTP & 1) {
        int nt = NTP - 1;
        int ng = (pb * NTP + nt) * 8 + cb;
        float2 bv = *(const float2*)(bias + ng);
        float c0 = bv.x, c1 = bv.y, c2 = bv.x, c3 = bv.y;
        const ull* ph = shi + nt * 32 + lane;
        const ull* pl = slo + nt * 32 + lane;
#pragma unroll
        for (int kt = 0; kt < KT; kt++) {
            ull bh = ph[kt * NTP * 32];
            ull bl = pl[kt * NTP * 32];
            unsigned bh0 = (unsigned)bh, bh1 = (unsigned)(bh >> 32);
            unsigned bl0 = (unsigned)bl, bl1 = (unsigned)(bl >> 32);
            mma16816(c0, c1, c2, c3, ahi[kt], bl0, bl1);
            mma16816(c0, c1, c2, c3, alo[kt], bh0, bh1);
            mma16816(c0, c1, c2, c3, ahi[kt], bh0, bh1);
        }
        *(float2*)(out + (size_t)r0 * G + ng) = make_float2(c0, c1);
        *(float2*)(out + (size_t)r1 * G + ng) = make_float2(c2, c3);
    }
}

// ---------------------------------------------------------------------------
// Persistent FFMA2 LSTM (round-9 configuration — measured best).
// ---------------------------------------------------------------------------
template<int H, int RSP, bool LAST_ONLY>
__global__ __launch_bounds__(224, 1)
void lstm_kernel(const float* __restrict__ pre, const float* __restrict__ whhT,
                 float* __restrict__ hout) {
    constexpr int G    = 4 * H;
    constexpr int NCG  = G / 2;
    constexpr int NACT = RSP * NCG;
    constexpr int RPT  = 8 / RSP;
    constexpr int NQ   = RPT / 2;
    constexpr int UPT  = 8 * H / NACT;
    constexpr int RPS  = 13;
    constexpr int RPH  = 12;

    extern __shared__ float sm[];
    float* sw  = sm;
    float* sgt = sm + H * G;
    float* shp = sgt + G * RPS;

    int tid = threadIdx.x;
    int b0  = blockIdx.x * 8;

    for (int i = tid; i < H * G; i += blockDim.x) sw[i] = whhT[i];
    for (int i = tid; i < H * RPH; i += blockDim.x) shp[i] = 0.0f;
    __syncthreads();

    bool gate = (tid < NACT);
    int rg = 0, cg = 0;
    if (gate) { rg = tid / NCG; cg = tid - rg * NCG; }
    int r0 = rg * RPT;
    int c0 = 2 * cg;

    int ur[UPT], uj[UPT];
#pragma unroll
    for (int i = 0; i < UPT; i++) {
        int u = tid + i * NACT;
        ur[i] = u / H; uj[i] = u - ur[i] * H;
    }
    float cst[UPT];
#pragma unroll
    for (int i = 0; i < UPT; i++) cst[i] = 0.0f;

    float pv[RPT][2];
    if (gate) {
#pragma unroll
        for (int r = 0; r < RPT; r++) {
            float2 v = *(const float2*)(pre + ((size_t)(b0 + r0 + r) * TT) * G + c0);
            pv[r][0] = v.x; pv[r][1] = v.y;
        }
    }

    for (int t = 0; t < TT; t++) {
        if (gate) {
            ull acc[NQ][2];
#pragma unroll
            for (int q = 0; q < NQ; q++) {
                acc[q][0] = pk(pv[2 * q][0], pv[2 * q + 1][0]);
                acc[q][1] = pk(pv[2 * q][1], pv[2 * q + 1][1]);
            }
            int tn = (t + 1 < TT) ? t + 1 : t;
#pragma unroll
            for (int r = 0; r < RPT; r++) {
                float2 v = *(const float2*)(pre + ((size_t)(b0 + r0 + r) * TT + tn) * G + c0);
                pv[r][0] = v.x; pv[r][1] = v.y;
            }

#pragma unroll 4
            for (int k = 0; k < H; k++) {
                const float* hp = shp + k * RPH + r0;
                float2 w = *(const float2*)(sw + k * G + c0);
                ull w0 = dup2(w.x), w1 = dup2(w.y);
                if (RPT == 8) {
                    ulonglong2 hA = *(const ulonglong2*)(hp);
                    ulonglong2 hB = *(const ulonglong2*)(hp + 4);
                    acc[0][0] = ffma2(acc[0][0], hA.x, w0); acc[0][1] = ffma2(acc[0][1], hA.x, w1);
                    acc[1][0] = ffma2(acc[1][0], hA.y, w0); acc[1][1] = ffma2(acc[1][1], hA.y, w1);
                    acc[2][0] = ffma2(acc[2][0], hB.x, w0); acc[2][1] = ffma2(acc[2][1], hB.x, w1);
                    acc[3][0] = ffma2(acc[3][0], hB.y, w0); acc[3][1] = ffma2(acc[3][1], hB.y, w1);
                } else {
                    ulonglong2 hA = *(const ulonglong2*)(hp);
                    acc[0][0] = ffma2(acc[0][0], hA.x, w0); acc[0][1] = ffma2(acc[0][1], hA.x, w1);
                    acc[1][0] = ffma2(acc[1][0], hA.y, w0); acc[1][1] = ffma2(acc[1][1], hA.y, w1);
                }
            }
#pragma unroll
            for (int q = 0; q < NQ; q++) {
                *(ull*)(sgt + c0 * RPS + r0 + 2 * q) = acc[q][0];
                float f0, f1; upk(acc[q][1], f0, f1);
                sgt[(c0 + 1) * RPS + r0 + 2 * q]     = f0;
                sgt[(c0 + 1) * RPS + r0 + 2 * q + 1] = f1;
            }
        }
        __syncthreads();

        if (tid < NACT) {
#pragma unroll
            for (int i = 0; i < UPT; i++) {
                int r = ur[i], j = uj[i];
                float ig = sigm_m(sgt[(0 * H + j) * RPS + r]);
                float fg = sigm_m(sgt[(1 * H + j) * RPS + r]);
                float gg = tanh_m(sgt[(2 * H + j) * RPS + r]);
                float og = sigm_m(sgt[(3 * H + j) * RPS + r]);
                float c  = fg * cst[i] + ig * gg;
                cst[i] = c;
                float h  = og * tanh_m(c);
                shp[j * RPH + r] = h;
                if (!LAST_ONLY) {
                    hout[((size_t)(b0 + r) * TT + t) * H + j] = h;
                } else if (t == TT - 1) {
                    hout[(size_t)(b0 + r) * H + j] = h;
                }
            }
        }
        __syncthreads();
    }
}

// ---------------------------------------------------------------------------
// Launch
// ---------------------------------------------------------------------------
extern "C" void kernel_launch(void* const* d_in, const int* in_sizes, int n_in,
                              void* d_out, int out_size) {
    const float* x    = (const float*)d_in[0];
    const float* Wih1 = (const float*)d_in[1];
    const float* Whh1 = (const float*)d_in[2];
    const float* bih1 = (const float*)d_in[3];
    const float* bhh1 = (const float*)d_in[4];
    const float* Wih2 = (const float*)d_in[5];
    const float* Whh2 = (const float*)d_in[6];
    const float* bih2 = (const float*)d_in[7];
    const float* bhh2 = (const float*)d_in[8];
    float* out = (float*)d_out;
    (void)in_sizes; (void)n_in; (void)out_size;

    void *pre1, *h1, *pre2, *w1fh, *w1fl, *w2fh, *w2fl, *whh1T, *whh2T, *b1, *b2;
    cudaGetSymbolAddress(&pre1,  g_pre1);
    cudaGetSymbolAddress(&h1,    g_h1);
    cudaGetSymbolAddress(&pre2,  g_pre2);
    cudaGetSymbolAddress(&w1fh,  g_w1fh);
    cudaGetSymbolAddress(&w1fl,  g_w1fl);
    cudaGetSymbolAddress(&w2fh,  g_w2fh);
    cudaGetSymbolAddress(&w2fl,  g_w2fl);
    cudaGetSymbolAddress(&whh1T, g_whh1T);
    cudaGetSymbolAddress(&whh2T, g_whh2T);
    cudaGetSymbolAddress(&b1,    g_b1);
    cudaGetSymbolAddress(&b2,    g_b2);

    const int SMEM_G1 = 2 * 5 * 25 * 32 * 8;                          //  64000
    const int SMEM_G2 = 2 * 7 * 25 * 32 * 8;                          //  89600
    const int SMEM_L1 = NH1 * NG1 * 4 + NG1 * 13 * 4 + NH1 * 12 * 4;  // 185600
    const int SMEM_L2 = NH2 * NG2 * 4 + NG2 * 13 * 4 + NH2 * 12 * 4;  //  52800

    cudaFuncSetAttribute(mma_gemm<5, 25, IN1, NG1>, cudaFuncAttributeMaxDynamicSharedMemorySize, SMEM_G1);
    cudaFuncSetAttribute(mma_gemm<7, 25, NH1, NG2>, cudaFuncAttributeMaxDynamicSharedMemorySize, SMEM_G2);
    cudaFuncSetAttribute(lstm_kernel<NH1, 1, false>, cudaFuncAttributeMaxDynamicSharedMemorySize, SMEM_L1);
    cudaFuncSetAttribute(lstm_kernel<NH2, 2, true>,  cudaFuncAttributeMaxDynamicSharedMemorySize, SMEM_L2);

    prep_kernel<<<96, 256>>>(Wih1, Whh1, bih1, bhh1, Wih2, Whh2, bih2, bhh2);

    mma_gemm<5, 25, IN1, NG1><<<dim3(BB * TT / 128, 2), 256, SMEM_G1>>>(
        x, (const ull*)w1fh, (const ull*)w1fl, (const float*)b1, (float*)pre1);

    lstm_kernel<NH1, 1, false><<<BB / 8, 224, SMEM_L1>>>(
        (const float*)pre1, (const float*)whh1T, (float*)h1);

    mma_gemm<7, 25, NH1, NG2><<<dim3(BB * TT / 128, 1), 256, SMEM_G2>>>(
        (const float*)h1, (const ull*)w2fh, (const ull*)w2fl, (const float*)b2, (float*)pre2);

    lstm_kernel<NH2, 2, true><<<BB / 8, 224, SMEM_L2>>>(
        (const float*)pre2, (const float*)whh2T, out);
}

// round 14
// speedup vs baseline: 1.0310x; 1.0310x over previous
#include <cuda_runtime.h>

// ---------------------------------------------------------------------------
// Problem constants
// ---------------------------------------------------------------------------
#define TT   512
#define BB   1024
#define IN1  80
#define NH1  100
#define NG1  400
#define NH2  50
#define NG2  200

typedef unsigned long long ull;

// ---------------------------------------------------------------------------
// Device scratch
// ---------------------------------------------------------------------------
__device__ __align__(16) float g_pre1[(size_t)BB * TT * NG1];   // [b][t][400]
__device__ __align__(16) float g_h1  [(size_t)BB * TT * NH1];   // [b][t][100]
__device__ __align__(16) float g_pre2[(size_t)BB * TT * NG2];   // [b][t][200]

// MMA frag-ordered weights (bf16 hi/lo splits), layout [panel][kt][nt][lane]
__device__ __align__(16) ull g_w1fh[2 * 5 * 25 * 32];   // gemm1 hi
__device__ __align__(16) ull g_w1fl[2 * 5 * 25 * 32];   // gemm1 lo
__device__ __align__(16) ull g_w2fh[7 * 25 * 32];       // gemm2 hi (K padded 112)
__device__ __align__(16) ull g_w2fl[7 * 25 * 32];       // gemm2 lo
// LSTM recurrent weights: plain [k][g]
__device__ __align__(16) float g_whh1T[NH1 * NG1];
__device__ __align__(16) float g_whh2T[NH2 * NG2];
// Fused biases, zero-padded
__device__ __align__(16) float g_b1[512];
__device__ __align__(16) float g_b2[512];

// ---------------------------------------------------------------------------
// helpers
// ---------------------------------------------------------------------------
__device__ __forceinline__ ull ffma2(ull d, ull a, ull b) {
    asm("fma.rn.f32x2 %0, %1, %2, %0;" : "+l"(d) : "l"(a), "l"(b));
    return d;
}
__device__ __forceinline__ ull dup2(float x) {
    ull r; unsigned u = __float_as_uint(x);
    asm("mov.b64 %0, {%1, %1};" : "=l"(r) : "r"(u));
    return r;
}
__device__ __forceinline__ ull pk(float x, float y) {
    ull r;
    asm("mov.b64 %0, {%1, %2};" : "=l"(r) : "f"(x), "f"(y));
    return r;
}
__device__ __forceinline__ void upk(ull v, float& a, float& b) {
    unsigned lo, hi;
    asm("mov.b64 {%0, %1}, %2;" : "=r"(lo), "=r"(hi) : "l"(v));
    a = __uint_as_float(lo); b = __uint_as_float(hi);
}
// pack two f32 into bf16x2: first arg -> UPPER half, second -> LOWER half
__device__ __forceinline__ unsigned pkbf(float hi_elem, float lo_elem) {
    unsigned r;
    asm("cvt.rn.bf16x2.f32 %0, %1, %2;" : "=r"(r) : "f"(hi_elem), "f"(lo_elem));
    return r;
}
__device__ __forceinline__ float bflo_f(unsigned p) { return __uint_as_float(p << 16); }
__device__ __forceinline__ float bfhi_f(unsigned p) { return __uint_as_float(p & 0xffff0000u); }

// m16n8k16 row.col bf16 MMA, fp32 accumulate
__device__ __forceinline__ void mma16816(float& c0, float& c1, float& c2, float& c3,
                                         const unsigned* a, unsigned b0, unsigned b1) {
    asm volatile(
        "mma.sync.aligned.m16n8k16.row.col.f32.bf16.bf16.f32 "
        "{%0,%1,%2,%3}, {%4,%5,%6,%7}, {%8,%9}, {%0,%1,%2,%3};"
        : "+f"(c0), "+f"(c1), "+f"(c2), "+f"(c3)
        : "r"(a[0]), "r"(a[1]), "r"(a[2]), "r"(a[3]), "r"(b0), "r"(b1));
}

// MUFU-based activations (tanh.approx: 1 MUFU, ~2^-11 abs err)
__device__ __forceinline__ float tanh_m(float x) {
    float r; asm("tanh.approx.f32 %0, %1;" : "=f"(r) : "f"(x));
    return r;
}
__device__ __forceinline__ float sigm_m(float x) {
    return fmaf(0.5f, tanh_m(0.5f * x), 0.5f);
}

// ---------------------------------------------------------------------------
// prep: build frag-ordered bf16 hi/lo weights, LSTM weights, biases
// ---------------------------------------------------------------------------
__global__ void prep_kernel(const float* __restrict__ Wih1, const float* __restrict__ Whh1,
                            const float* __restrict__ bih1, const float* __restrict__ bhh1,
                            const float* __restrict__ Wih2, const float* __restrict__ Whh2,
                            const float* __restrict__ bih2, const float* __restrict__ bhh2) {
    int tid = blockIdx.x * blockDim.x + threadIdx.x;
    int stride = gridDim.x * blockDim.x;

    for (int i = tid; i < 2 * 5 * 25 * 32; i += stride) {
        int l = i & 31, t = i >> 5;
        int nt = t % 25; t /= 25;
        int kt = t % 5;  int p = t / 5;
        int n  = (p * 25 + nt) * 8 + (l >> 2);
        int k0 = 16 * kt + 2 * (l & 3);
        float w0 = Wih1[n * IN1 + k0];
        float w1 = Wih1[n * IN1 + k0 + 1];
        float w2 = Wih1[n * IN1 + k0 + 8];
        float w3 = Wih1[n * IN1 + k0 + 9];
        unsigned h0 = pkbf(w1, w0), h1 = pkbf(w3, w2);
        unsigned l0 = pkbf(w1 - bfhi_f(h0), w0 - bflo_f(h0));
        unsigned l1 = pkbf(w3 - bfhi_f(h1), w2 - bflo_f(h1));
        g_w1fh[i] = (ull)h0 | ((ull)h1 << 32);
        g_w1fl[i] = (ull)l0 | ((ull)l1 << 32);
    }
    for (int i = tid; i < 7 * 25 * 32; i += stride) {
        int l = i & 31, t = i >> 5;
        int nt = t % 25;
        int kt = t / 25;
        int n  = nt * 8 + (l >> 2);
        int k0 = 16 * kt + 2 * (l & 3);
        float w0 = (k0     < NH1) ? Wih2[n * NH1 + k0]     : 0.0f;
        float w1 = (k0 + 1 < NH1) ? Wih2[n * NH1 + k0 + 1] : 0.0f;
        float w2 = (k0 + 8 < NH1) ? Wih2[n * NH1 + k0 + 8] : 0.0f;
        float w3 = (k0 + 9 < NH1) ? Wih2[n * NH1 + k0 + 9] : 0.0f;
        unsigned h0 = pkbf(w1, w0), h1 = pkbf(w3, w2);
        unsigned l0 = pkbf(w1 - bfhi_f(h0), w0 - bflo_f(h0));
        unsigned l1 = pkbf(w3 - bfhi_f(h1), w2 - bflo_f(h1));
        g_w2fh[i] = (ull)h0 | ((ull)h1 << 32);
        g_w2fl[i] = (ull)l0 | ((ull)l1 << 32);
    }
    for (int i = tid; i < NH1 * NG1; i += stride) { int k = i / NG1, g = i % NG1; g_whh1T[i] = Whh1[g * NH1 + k]; }
    for (int i = tid; i < NH2 * NG2; i += stride) { int k = i / NG2, g = i % NG2; g_whh2T[i] = Whh2[g * NH2 + k]; }
    for (int i = tid; i < 512; i += stride) {
        g_b1[i] = (i < NG1) ? bih1[i] + bhh1[i] : 0.0f;
        g_b2[i] = (i < NG2) ? bih2[i] + bhh2[i] : 0.0f;
    }
}

// ---------------------------------------------------------------------------
// Tensor-core GEMM (R7/R9 configuration — measured 210us).
// ---------------------------------------------------------------------------
template<int KT, int NTP, int KREAL, int G>
__global__ __launch_bounds__(256, 2)
void mma_gemm(const float* __restrict__ x, const ull* __restrict__ wfh,
              const ull* __restrict__ wfl, const float* __restrict__ bias,
              float* __restrict__ out) {
    constexpr int K = KT * 16;
    constexpr int NFRAG = KT * NTP * 32;
    extern __shared__ ull smw[];
    ull* shi = smw;
    ull* slo = smw + NFRAG;

    int tid  = threadIdx.x;
    int lane = tid & 31;
    int wi   = tid >> 5;
    int m0   = blockIdx.x * 128;
    int pb   = blockIdx.y;

    const ull* srch = wfh + (size_t)pb * NFRAG;
    const ull* srcl = wfl + (size_t)pb * NFRAG;
    for (int i = tid; i < NFRAG; i += 256) { shi[i] = srch[i]; slo[i] = srcl[i]; }
    __syncthreads();

    int r0 = m0 + wi * 16 + (lane >> 2);
    int r1 = r0 + 8;
    int cb = 2 * (lane & 3);

    unsigned ahi[KT][4], alo[KT][4];
#pragma unroll
    for (int kt = 0; kt < KT; kt++) {
#pragma unroll
        for (int q = 0; q < 4; q++) {
            int rr = (q & 1) ? r1 : r0;
            int cc = 16 * kt + cb + (q >> 1) * 8;
            float2 v = make_float2(0.0f, 0.0f);
            if (K == KREAL || cc + 2 <= KREAL)
                v = *(const float2*)(x + (size_t)rr * KREAL + cc);
            unsigned h = pkbf(v.y, v.x);
            ahi[kt][q] = h;
            alo[kt][q] = pkbf(v.y - bfhi_f(h), v.x - bflo_f(h));
        }
    }

    for (int nt = 0; nt < NTP; nt++) {
        int ng = (pb * NTP + nt) * 8 + cb;
        float2 bv = *(const float2*)(bias + ng);
        float c0 = bv.x, c1 = bv.y, c2 = bv.x, c3 = bv.y;
        const ull* ph = shi + nt * 32 + lane;
        const ull* pl = slo + nt * 32 + lane;
#pragma unroll
        for (int kt = 0; kt < KT; kt++) {
            ull bh = ph[kt * NTP * 32];
            ull bl = pl[kt * NTP * 32];
            unsigned bh0 = (unsigned)bh, bh1 = (unsigned)(bh >> 32);
            unsigned bl0 = (unsigned)bl, bl1 = (unsigned)(bl >> 32);
            mma16816(c0, c1, c2, c3, ahi[kt], bl0, bl1);   // hi * lo
            mma16816(c0, c1, c2, c3, alo[kt], bh0, bh1);   // lo * hi
            mma16816(c0, c1, c2, c3, ahi[kt], bh0, bh1);   // hi * hi
        }
        *(float2*)(out + (size_t)r0 * G + ng) = make_float2(c0, c1);
        *(float2*)(out + (size_t)r1 * G + ng) = make_float2(c2, c3);
    }
}

// ---------------------------------------------------------------------------
// Persistent FFMA2 LSTM v3: k-split for warp-parallelism.
// 8 batch rows/CTA, 128 CTAs, 416 threads.
// Gate: NACT = KSPLIT*RSP*(G/2) = 400 threads (12.5 warps, 3.1/SMSP).
//   Thread (ks, rg, cg): RPT=8/RSP rows x 2 cols over k in [ks*H/KSPLIT, ...).
//   Per k: RPT/4 broadcast LDS.128 (h) + coalesced LDS.64 (w) + RPT FFMA2.
//   Total LDS wf/step unchanged vs KSPLIT=1 (k halves, warps double).
// Staging: sgt[ks][col][13]; even col ull store, odd col 2x STS.32 (13 odd).
// Update: sums KSPLIT partials; MUFU activations.
// ---------------------------------------------------------------------------
template<int H, int RSP, int KSPLIT, bool LAST_ONLY>
__global__ __launch_bounds__(416, 1)
void lstm_kernel(const float* __restrict__ pre, const float* __restrict__ whhT,
                 float* __restrict__ hout) {
    constexpr int G    = 4 * H;
    constexpr int NCG  = G / 2;                 // col-threads per (ks, rg)
    constexpr int NGRP = RSP * NCG;             // threads per k-split
    constexpr int NACT = KSPLIT * NGRP;         // 400 for both layers
    constexpr int RPT  = 8 / RSP;               // rows per thread
    constexpr int NQ   = RPT / 2;               // row-pairs per thread
    constexpr int KH   = H / KSPLIT;            // k per split
    constexpr int UPT  = 8 * H / NACT;          // update units per thread
    constexpr int RPS  = 13;                    // sgt row pad (conflict-free)
    constexpr int RPH  = 12;                    // shp row pad (16B aligned)

    extern __shared__ float sm[];
    float* sw  = sm;                            // [H][G]
    float* sgt = sm + H * G;                    // [KSPLIT][G][13]
    float* shp = sgt + KSPLIT * G * RPS;        // [H][12]

    int tid = threadIdx.x;
    int b0  = blockIdx.x * 8;

    for (int i = tid; i < H * G; i += blockDim.x) sw[i] = whhT[i];
    for (int i = tid; i < H * RPH; i += blockDim.x) shp[i] = 0.0f;
    __syncthreads();

    bool gate = (tid < NACT);
    int ks = 0, rg = 0, cg = 0;
    if (gate) {
        ks = tid / NGRP;
        int rem = tid - ks * NGRP;
        rg = rem / NCG; cg = rem - rg * NCG;
    }
    int r0 = rg * RPT;
    int c0 = 2 * cg;
    int k0 = ks * KH;
    float* sgtp = sgt + ks * G * RPS;

    // update mapping: u = tid + i*NACT; j = tid % H (constant), r = u / H
    int uj = tid % H;
    int ur[UPT];
#pragma unroll
    for (int i = 0; i < UPT; i++) ur[i] = (tid + i * NACT) / H;
    float cst[UPT];
#pragma unroll
    for (int i = 0; i < UPT; i++) cst[i] = 0.0f;

    // ks==0 threads own the pre for their rows
    float pv[RPT][2];
    if (gate && ks == 0) {
#pragma unroll
        for (int r = 0; r < RPT; r++) {
            float2 v = *(const float2*)(pre + ((size_t)(b0 + r0 + r) * TT) * G + c0);
            pv[r][0] = v.x; pv[r][1] = v.y;
        }
    }

    for (int t = 0; t < TT; t++) {
        if (gate) {
            ull acc[NQ][2];
            if (ks == 0) {
#pragma unroll
                for (int q = 0; q < NQ; q++) {
                    acc[q][0] = pk(pv[2 * q][0], pv[2 * q + 1][0]);
                    acc[q][1] = pk(pv[2 * q][1], pv[2 * q + 1][1]);
                }
                int tn = (t + 1 < TT) ? t + 1 : t;
#pragma unroll
                for (int r = 0; r < RPT; r++) {
                    float2 v = *(const float2*)(pre + ((size_t)(b0 + r0 + r) * TT + tn) * G + c0);
                    pv[r][0] = v.x; pv[r][1] = v.y;
                }
            } else {
#pragma unroll
                for (int q = 0; q < NQ; q++) { acc[q][0] = 0ULL; acc[q][1] = 0ULL; }
            }

#pragma unroll 4
            for (int k = k0; k < k0 + KH; k++) {
                const float* hp = shp + k * RPH + r0;
                float2 w = *(const float2*)(sw + k * G + c0);
                ull w0 = dup2(w.x), w1 = dup2(w.y);
                if (RPT == 8) {
                    ulonglong2 hA = *(const ulonglong2*)(hp);       // rows 0-3
                    ulonglong2 hB = *(const ulonglong2*)(hp + 4);   // rows 4-7
                    acc[0][0] = ffma2(acc[0][0], hA.x, w0); acc[0][1] = ffma2(acc[0][1], hA.x, w1);
                    acc[1][0] = ffma2(acc[1][0], hA.y, w0); acc[1][1] = ffma2(acc[1][1], hA.y, w1);
                    acc[2][0] = ffma2(acc[2][0], hB.x, w0); acc[2][1] = ffma2(acc[2][1], hB.x, w1);
                    acc[3][0] = ffma2(acc[3][0], hB.y, w0); acc[3][1] = ffma2(acc[3][1], hB.y, w1);
                } else {
                    ulonglong2 hA = *(const ulonglong2*)(hp);       // RPT=4 rows
                    acc[0][0] = ffma2(acc[0][0], hA.x, w0); acc[0][1] = ffma2(acc[0][1], hA.x, w1);
                    acc[1][0] = ffma2(acc[1][0], hA.y, w0); acc[1][1] = ffma2(acc[1][1], hA.y, w1);
                }
            }
            // even column: ull store (even idx); odd column: 2x STS.32
#pragma unroll
            for (int q = 0; q < NQ; q++) {
                *(ull*)(sgtp + c0 * RPS + r0 + 2 * q) = acc[q][0];
                float f0, f1; upk(acc[q][1], f0, f1);
                sgtp[(c0 + 1) * RPS + r0 + 2 * q]     = f0;
                sgtp[(c0 + 1) * RPS + r0 + 2 * q + 1] = f1;
            }
        }
        __syncthreads();

        if (tid < NACT) {
#pragma unroll
            for (int i = 0; i < UPT; i++) {
                int r = ur[i], j = uj;
                float gs[4];
#pragma unroll
                for (int gix = 0; gix < 4; gix++) {
                    float s = sgt[(gix * H + j) * RPS + r];
#pragma unroll
                    for (int k2 = 1; k2 < KSPLIT; k2++)
                        s += sgt[k2 * G * RPS + (gix * H + j) * RPS + r];
                    gs[gix] = s;
                }
                float ig = sigm_m(gs[0]);
                float fg = sigm_m(gs[1]);
                float gg = tanh_m(gs[2]);
                float og = sigm_m(gs[3]);
                float c  = fg * cst[i] + ig * gg;
                cst[i] = c;
                float h  = og * tanh_m(c);
                shp[j * RPH + r] = h;
                if (!LAST_ONLY) {
                    hout[((size_t)(b0 + r) * TT + t) * H + j] = h;
                } else if (t == TT - 1) {
                    hout[(size_t)(b0 + r) * H + j] = h;
                }
            }
        }
        __syncthreads();
    }
}

// ---------------------------------------------------------------------------
// Launch
// ---------------------------------------------------------------------------
extern "C" void kernel_launch(void* const* d_in, const int* in_sizes, int n_in,
                              void* d_out, int out_size) {
    const float* x    = (const float*)d_in[0];
    const float* Wih1 = (const float*)d_in[1];
    const float* Whh1 = (const float*)d_in[2];
    const float* bih1 = (const float*)d_in[3];
    const float* bhh1 = (const float*)d_in[4];
    const float* Wih2 = (const float*)d_in[5];
    const float* Whh2 = (const float*)d_in[6];
    const float* bih2 = (const float*)d_in[7];
    const float* bhh2 = (const float*)d_in[8];
    float* out = (float*)d_out;
    (void)in_sizes; (void)n_in; (void)out_size;

    void *pre1, *h1, *pre2, *w1fh, *w1fl, *w2fh, *w2fl, *whh1T, *whh2T, *b1, *b2;
    cudaGetSymbolAddress(&pre1,  g_pre1);
    cudaGetSymbolAddress(&h1,    g_h1);
    cudaGetSymbolAddress(&pre2,  g_pre2);
    cudaGetSymbolAddress(&w1fh,  g_w1fh);
    cudaGetSymbolAddress(&w1fl,  g_w1fl);
    cudaGetSymbolAddress(&w2fh,  g_w2fh);
    cudaGetSymbolAddress(&w2fl,  g_w2fl);
    cudaGetSymbolAddress(&whh1T, g_whh1T);
    cudaGetSymbolAddress(&whh2T, g_whh2T);
    cudaGetSymbolAddress(&b1,    g_b1);
    cudaGetSymbolAddress(&b2,    g_b2);

    const int SMEM_G1 = 2 * 5 * 25 * 32 * 8;                              //  64000
    const int SMEM_G2 = 2 * 7 * 25 * 32 * 8;                              //  89600
    const int SMEM_L1 = NH1 * NG1 * 4 + 2 * NG1 * 13 * 4 + NH1 * 12 * 4;  // 206400
    const int SMEM_L2 = NH2 * NG2 * 4 + 2 * NG2 * 13 * 4 + NH2 * 12 * 4;  //  63200

    cudaFuncSetAttribute(mma_gemm<5, 25, IN1, NG1>, cudaFuncAttributeMaxDynamicSharedMemorySize, SMEM_G1);
    cudaFuncSetAttribute(mma_gemm<7, 25, NH1, NG2>, cudaFuncAttributeMaxDynamicSharedMemorySize, SMEM_G2);
    cudaFuncSetAttribute(lstm_kernel<NH1, 1, 2, false>, cudaFuncAttributeMaxDynamicSharedMemorySize, SMEM_L1);
    cudaFuncSetAttribute(lstm_kernel<NH2, 2, 2, true>,  cudaFuncAttributeMaxDynamicSharedMemorySize, SMEM_L2);

    prep_kernel<<<96, 256>>>(Wih1, Whh1, bih1, bhh1, Wih2, Whh2, bih2, bhh2);

    mma_gemm<5, 25, IN1, NG1><<<dim3(BB * TT / 128, 2), 256, SMEM_G1>>>(
        x, (const ull*)w1fh, (const ull*)w1fl, (const float*)b1, (float*)pre1);

    lstm_kernel<NH1, 1, 2, false><<<BB / 8, 416, SMEM_L1>>>(
        (const float*)pre1, (const float*)whh1T, (float*)h1);

    mma_gemm<7, 25, NH1, NG2><<<dim3(BB * TT / 128, 1), 256, SMEM_G2>>>(
        (const float*)h1, (const ull*)w2fh, (const ull*)w2fl, (const float*)b2, (float*)pre2);

    lstm_kernel<NH2, 2, 2, true><<<BB / 8, 416, SMEM_L2>>>(
        (const float*)pre2, (const float*)whh2T, out);
}